// round 3
// baseline (speedup 1.0000x reference)
#include <cuda_runtime.h>
#include <math.h>

// Problem constants
#define BB   2
#define TT   2048
#define CC   1024
#define NH   16
#define HD   64
#define BT   (BB * TT)        // 4096
#define KQV3 (3 * CC)         // 3072

// Scratch (allocation-free rule: __device__ globals)
__device__ float g_kqv[(size_t)BT * KQV3];  // (B,T,nh,3,hd) packed = 48 MB
__device__ float g_y[(size_t)BT * CC];      // attention output, 16 MB

// ---------------------------------------------------------------------------
// GEMM: C[m,n] = sum_k A[m,k] * W[n,k] + bias[n]
// A: M x K row-major, W: N x K row-major. M,N % 128 == 0, K % 8 == 0.
// BM=BN=128, BK=8, TM=TN=8, 256 threads.
// ---------------------------------------------------------------------------
__global__ __launch_bounds__(256)
void gemm_nt_bias(const float* __restrict__ A, const float* __restrict__ W,
                  const float* __restrict__ bias, float* __restrict__ Cmat,
                  int M, int N, int K) {
    __shared__ float As[8][132];
    __shared__ float Bs[8][132];

    const int tid = threadIdx.x;
    const int tx  = tid & 15;        // 0..15 -> n micro
    const int ty  = tid >> 4;        // 0..15 -> m micro
    const int m0  = blockIdx.y * 128;
    const int n0  = blockIdx.x * 128;

    const int lrow = tid >> 1;       // 0..127
    const int lk4  = (tid & 1) << 2; // 0 or 4

    float acc[8][8];
    #pragma unroll
    for (int i = 0; i < 8; i++)
        #pragma unroll
        for (int j = 0; j < 8; j++) acc[i][j] = 0.0f;

    const float* Aptr = A + (size_t)(m0 + lrow) * K + lk4;
    const float* Wptr = W + (size_t)(n0 + lrow) * K + lk4;

    for (int k0 = 0; k0 < K; k0 += 8) {
        float4 a4 = *reinterpret_cast<const float4*>(Aptr + k0);
        float4 b4 = *reinterpret_cast<const float4*>(Wptr + k0);
        As[lk4 + 0][lrow] = a4.x; As[lk4 + 1][lrow] = a4.y;
        As[lk4 + 2][lrow] = a4.z; As[lk4 + 3][lrow] = a4.w;
        Bs[lk4 + 0][lrow] = b4.x; Bs[lk4 + 1][lrow] = b4.y;
        Bs[lk4 + 2][lrow] = b4.z; Bs[lk4 + 3][lrow] = b4.w;
        __syncthreads();

        #pragma unroll
        for (int kk = 0; kk < 8; kk++) {
            float ra[8], rb[8];
            #pragma unroll
            for (int i = 0; i < 8; i++) ra[i] = As[kk][ty * 8 + i];
            #pragma unroll
            for (int j = 0; j < 8; j++) rb[j] = Bs[kk][tx * 8 + j];
            #pragma unroll
            for (int i = 0; i < 8; i++)
                #pragma unroll
                for (int j = 0; j < 8; j++)
                    acc[i][j] = fmaf(ra[i], rb[j], acc[i][j]);
        }
        __syncthreads();
    }

    #pragma unroll
    for (int i = 0; i < 8; i++) {
        const int m = m0 + ty * 8 + i;
        #pragma unroll
        for (int j = 0; j < 8; j++) {
            const int n = n0 + tx * 8 + j;
            Cmat[(size_t)m * N + n] = acc[i][j] + bias[n];
        }
    }
}

// ---------------------------------------------------------------------------
// Flash attention (fp32, online softmax).
// Grid: (T/64, NH, B). Block: 256 threads (16x16), 4x4 micro-tile.
// smem: Qs[64][68], KP[64][68] (K tile, then reused for P), Vs[64][68].
// ---------------------------------------------------------------------------
#define ATT_STRIDE 68
#define ATT_SMEM   (3 * 64 * ATT_STRIDE * sizeof(float))  // 52224 B

__global__ __launch_bounds__(256)
void attn_kernel(const float* __restrict__ kqv, float* __restrict__ y) {
    extern __shared__ float smem[];
    float* Qs = smem;
    float* KP = smem + 64 * ATT_STRIDE;
    float* Vs = smem + 2 * 64 * ATT_STRIDE;

    const int qb  = blockIdx.x;
    const int h   = blockIdx.y;
    const int b   = blockIdx.z;
    const int tid = threadIdx.x;
    const int tx  = tid & 15;   // key / hd column group
    const int ty  = tid >> 4;   // query row group
    const int q0  = qb * 64;
    const float scale = 0.125f; // 1/sqrt(64)

    // Load Q tile (sel = 1)
    for (int i4 = tid; i4 < 64 * 16; i4 += 256) {
        const int r  = i4 >> 4;
        const int c4 = (i4 & 15) << 2;
        const size_t base = (size_t)((b * TT + q0 + r) * NH + h) * (3 * HD);
        float4 v = *reinterpret_cast<const float4*>(&kqv[base + HD + c4]);
        float* dst = &Qs[r * ATT_STRIDE + c4];
        dst[0] = v.x; dst[1] = v.y; dst[2] = v.z; dst[3] = v.w;
    }

    float m_i[4], l_i[4], O[4][4];
    #pragma unroll
    for (int i = 0; i < 4; i++) {
        m_i[i] = -1e30f; l_i[i] = 0.0f;
        #pragma unroll
        for (int j = 0; j < 4; j++) O[i][j] = 0.0f;
    }
    __syncthreads();

    for (int kb = 0; kb <= qb; kb++) {
        const int k0 = kb * 64;
        // Load K (sel=0) and V (sel=2) tiles
        for (int i4 = tid; i4 < 64 * 16; i4 += 256) {
            const int r  = i4 >> 4;
            const int c4 = (i4 & 15) << 2;
            const size_t base = (size_t)((b * TT + k0 + r) * NH + h) * (3 * HD) + c4;
            float4 kv = *reinterpret_cast<const float4*>(&kqv[base]);
            float4 vv = *reinterpret_cast<const float4*>(&kqv[base + 2 * HD]);
            float* kd = &KP[r * ATT_STRIDE + c4];
            kd[0] = kv.x; kd[1] = kv.y; kd[2] = kv.z; kd[3] = kv.w;
            float* vd = &Vs[r * ATT_STRIDE + c4];
            vd[0] = vv.x; vd[1] = vv.y; vd[2] = vv.z; vd[3] = vv.w;
        }
        __syncthreads();

        // S = Q K^T (4x4 per thread)
        float s[4][4];
        #pragma unroll
        for (int i = 0; i < 4; i++)
            #pragma unroll
            for (int j = 0; j < 4; j++) s[i][j] = 0.0f;

        #pragma unroll 8
        for (int d = 0; d < 64; d++) {
            float qa[4], ka[4];
            #pragma unroll
            for (int i = 0; i < 4; i++) qa[i] = Qs[(ty * 4 + i) * ATT_STRIDE + d];
            #pragma unroll
            for (int j = 0; j < 4; j++) ka[j] = KP[(tx * 4 + j) * ATT_STRIDE + d];
            #pragma unroll
            for (int i = 0; i < 4; i++)
                #pragma unroll
                for (int j = 0; j < 4; j++)
                    s[i][j] = fmaf(qa[i], ka[j], s[i][j]);
        }

        // scale + causal mask (diagonal block only)
        const bool diag = (kb == qb);
        #pragma unroll
        for (int i = 0; i < 4; i++)
            #pragma unroll
            for (int j = 0; j < 4; j++) {
                if (diag && (tx * 4 + j) > (ty * 4 + i)) s[i][j] = -1e30f;
                else s[i][j] *= scale;
            }

        // online softmax update (row stats reduced over 16-thread tx group)
        #pragma unroll
        for (int i = 0; i < 4; i++) {
            float mx = s[i][0];
            #pragma unroll
            for (int j = 1; j < 4; j++) mx = fmaxf(mx, s[i][j]);
            #pragma unroll
            for (int off = 8; off >= 1; off >>= 1)
                mx = fmaxf(mx, __shfl_xor_sync(0xffffffffu, mx, off));
            const float mnew  = fmaxf(m_i[i], mx);
            const float alpha = __expf(m_i[i] - mnew);
            float rs = 0.0f;
            #pragma unroll
            for (int j = 0; j < 4; j++) {
                const float p = __expf(s[i][j] - mnew);
                s[i][j] = p;
                rs += p;
            }
            #pragma unroll
            for (int off = 8; off >= 1; off >>= 1)
                rs += __shfl_xor_sync(0xffffffffu, rs, off);
            l_i[i] = l_i[i] * alpha + rs;
            #pragma unroll
            for (int j = 0; j < 4; j++) O[i][j] *= alpha;
            m_i[i] = mnew;
        }

        __syncthreads();  // everyone done reading K tile
        // store P into KP
        #pragma unroll
        for (int i = 0; i < 4; i++)
            #pragma unroll
            for (int j = 0; j < 4; j++)
                KP[(ty * 4 + i) * ATT_STRIDE + tx * 4 + j] = s[i][j];
        __syncthreads();

        // O += P @ V
        #pragma unroll 8
        for (int c = 0; c < 64; c++) {
            float pa[4], vb[4];
            #pragma unroll
            for (int i = 0; i < 4; i++) pa[i] = KP[(ty * 4 + i) * ATT_STRIDE + c];
            #pragma unroll
            for (int j = 0; j < 4; j++) vb[j] = Vs[c * ATT_STRIDE + tx * 4 + j];
            #pragma unroll
            for (int i = 0; i < 4; i++)
                #pragma unroll
                for (int j = 0; j < 4; j++)
                    O[i][j] = fmaf(pa[i], vb[j], O[i][j]);
        }
        __syncthreads();  // before next tile overwrites KP/Vs
    }

    // normalize + write y (B,T,C) with head offset
    #pragma unroll
    for (int i = 0; i < 4; i++) {
        const float inv = 1.0f / l_i[i];
        const int t = q0 + ty * 4 + i;
        #pragma unroll
        for (int j = 0; j < 4; j++)
            y[(size_t)(b * TT + t) * CC + h * HD + tx * 4 + j] = O[i][j] * inv;
    }
}

// ---------------------------------------------------------------------------
extern "C" void kernel_launch(void* const* d_in, const int* in_sizes, int n_in,
                              void* d_out, int out_size) {
    (void)in_sizes; (void)n_in; (void)out_size;
    const float* x      = (const float*)d_in[0];
    const float* W_kqv  = (const float*)d_in[1];
    const float* b_kqv  = (const float*)d_in[2];
    const float* W_proj = (const float*)d_in[3];
    const float* b_proj = (const float*)d_in[4];
    float* out = (float*)d_out;

    float* kqv = nullptr;
    float* y   = nullptr;
    cudaGetSymbolAddress((void**)&kqv, g_kqv);
    cudaGetSymbolAddress((void**)&y, g_y);

    cudaFuncSetAttribute(attn_kernel, cudaFuncAttributeMaxDynamicSharedMemorySize,
                         (int)ATT_SMEM);

    // 1) kqv = x @ W_kqv^T + b_kqv   (M=4096, N=3072, K=1024)
    {
        dim3 grid(KQV3 / 128, BT / 128);
        gemm_nt_bias<<<grid, 256>>>(x, W_kqv, b_kqv, kqv, BT, KQV3, CC);
    }
    // 2) flash attention -> y
    {
        dim3 grid(TT / 64, NH, BB);
        attn_kernel<<<grid, 256, ATT_SMEM>>>(kqv, y);
    }
    // 3) out = y @ W_proj^T + b_proj (M=4096, N=1024, K=1024)
    {
        dim3 grid(CC / 128, BT / 128);
        gemm_nt_bias<<<grid, 256>>>(y, W_proj, b_proj, out, BT, CC, CC);
    }
}

// round 5
// speedup vs baseline: 2.4408x; 2.4408x over previous
#include <cuda_runtime.h>
#include <math.h>
#include <stdint.h>

// Problem constants
#define BB   2
#define TT   2048
#define CC   1024
#define NH   16
#define HD   64
#define BT   (BB * TT)        // 4096
#define KQV3 (3 * CC)         // 3072

// Scratch (allocation-free rule: __device__ globals)
__device__ float g_kqv[(size_t)BT * KQV3];  // (B,T,nh,3,hd) packed, fp32
__device__ float g_y[(size_t)BT * CC];      // attention output, fp32

// ---------------------------------------------------------------------------
// Helpers: tf32 convert + m16n8k8 tf32 mma
// ---------------------------------------------------------------------------
__device__ __forceinline__ uint32_t f2tf32(float x) {
    uint32_t r;
    asm("cvt.rna.tf32.f32 %0, %1;" : "=r"(r) : "f"(x));
    return r;
}

__device__ __forceinline__ void mma_tf32(float* c, const uint32_t* a,
                                         uint32_t b0, uint32_t b1) {
    asm volatile(
        "mma.sync.aligned.m16n8k8.row.col.f32.tf32.tf32.f32 "
        "{%0,%1,%2,%3}, {%4,%5,%6,%7}, {%8,%9}, {%0,%1,%2,%3};\n"
        : "+f"(c[0]), "+f"(c[1]), "+f"(c[2]), "+f"(c[3])
        : "r"(a[0]), "r"(a[1]), "r"(a[2]), "r"(a[3]), "r"(b0), "r"(b1));
}

// ---------------------------------------------------------------------------
// tf32 tensor-core GEMM: C[m,n] = sum_k A[m,k] * W[n,k] + bias[n]
// A: MxK row-major fp32, W: NxK row-major fp32.  M,N % 128 == 0, K % 16 == 0.
// BM=BN=128, BK=16. 256 threads = 8 warps in 2(m) x 4(n); warp tile 64x32.
// smem tiles stored [k][m] / [k][n] in tf32, stride 136 (8 mod 32 -> no
// bank conflicts on fragment loads).
// ---------------------------------------------------------------------------
#define GST 136

__global__ __launch_bounds__(256)
void gemm_tf32(const float* __restrict__ A, const float* __restrict__ W,
               const float* __restrict__ bias, float* __restrict__ Cmat,
               int M, int N, int K) {
    __shared__ uint32_t As[16][GST];
    __shared__ uint32_t Ws[16][GST];

    const int tid  = threadIdx.x;
    const int lane = tid & 31;
    const int wid  = tid >> 5;
    const int g    = lane >> 2;   // 0..7
    const int q    = lane & 3;    // 0..3
    const int wm   = wid >> 2;    // 0..1
    const int wn   = wid & 3;     // 0..3

    const int m0 = blockIdx.y * 128;
    const int n0 = blockIdx.x * 128;

    const float* Abase = A + (size_t)m0 * K;
    const float* Wbase = W + (size_t)n0 * K;

    float acc[4][4][4];
    #pragma unroll
    for (int mi = 0; mi < 4; mi++)
        #pragma unroll
        for (int ni = 0; ni < 4; ni++)
            #pragma unroll
            for (int r = 0; r < 4; r++) acc[mi][ni][r] = 0.0f;

    const int lm  = tid & 127;            // row within tile for loads
    const int lk4a = (tid >> 7) << 2;     // 0 or 4
    for (int kb = 0; kb < K; kb += 16) {
        // ---- load A,W tiles (transposed to [k][row], tf32) ----
        #pragma unroll
        for (int half = 0; half < 2; half++) {
            const int k4 = lk4a + half * 8;
            float4 av = *reinterpret_cast<const float4*>(
                Abase + (size_t)lm * K + kb + k4);
            As[k4 + 0][lm] = f2tf32(av.x);
            As[k4 + 1][lm] = f2tf32(av.y);
            As[k4 + 2][lm] = f2tf32(av.z);
            As[k4 + 3][lm] = f2tf32(av.w);
            float4 wv = *reinterpret_cast<const float4*>(
                Wbase + (size_t)lm * K + kb + k4);
            Ws[k4 + 0][lm] = f2tf32(wv.x);
            Ws[k4 + 1][lm] = f2tf32(wv.y);
            Ws[k4 + 2][lm] = f2tf32(wv.z);
            Ws[k4 + 3][lm] = f2tf32(wv.w);
        }
        __syncthreads();

        // ---- compute: 2 k-steps of 8 ----
        #pragma unroll
        for (int ks = 0; ks < 16; ks += 8) {
            uint32_t af[4][4];
            uint32_t bf[4][2];
            #pragma unroll
            for (int mi = 0; mi < 4; mi++) {
                const int m = wm * 64 + mi * 16;
                af[mi][0] = As[ks + q][m + g];
                af[mi][1] = As[ks + q][m + g + 8];
                af[mi][2] = As[ks + q + 4][m + g];
                af[mi][3] = As[ks + q + 4][m + g + 8];
            }
            #pragma unroll
            for (int ni = 0; ni < 4; ni++) {
                const int n = wn * 32 + ni * 8;
                bf[ni][0] = Ws[ks + q][n + g];
                bf[ni][1] = Ws[ks + q + 4][n + g];
            }
            #pragma unroll
            for (int mi = 0; mi < 4; mi++)
                #pragma unroll
                for (int ni = 0; ni < 4; ni++)
                    mma_tf32(acc[mi][ni], af[mi], bf[ni][0], bf[ni][1]);
        }
        __syncthreads();
    }

    // ---- epilogue: + bias, fp32 out ----
    #pragma unroll
    for (int mi = 0; mi < 4; mi++) {
        const int m = m0 + wm * 64 + mi * 16 + g;
        #pragma unroll
        for (int ni = 0; ni < 4; ni++) {
            const int n = n0 + wn * 32 + ni * 8 + 2 * q;
            const float b0 = __ldg(&bias[n]);
            const float b1 = __ldg(&bias[n + 1]);
            float2 v0 = make_float2(acc[mi][ni][0] + b0, acc[mi][ni][1] + b1);
            float2 v1 = make_float2(acc[mi][ni][2] + b0, acc[mi][ni][3] + b1);
            *reinterpret_cast<float2*>(&Cmat[(size_t)m * N + n]) = v0;
            *reinterpret_cast<float2*>(&Cmat[(size_t)(m + 8) * N + n]) = v1;
        }
    }
}

// ---------------------------------------------------------------------------
// Flash attention with tf32 mma. Grid (T/64, NH, B), 128 threads (4 warps).
// Each warp owns 16 q-rows. hd = 64.
// smem (uint32 words): sQ/sP [64][68], sK [64][72] ([hd][key], transposed),
// sV [64][72] ([key][hd]). All tf32.
// ---------------------------------------------------------------------------
#define QP_ST 68
#define KV_ST 72
#define ATT_SMEM_WORDS (64 * QP_ST + 2 * 64 * KV_ST)
#define ATT_SMEM_BYTES (ATT_SMEM_WORDS * 4)   // 54272

__global__ __launch_bounds__(128)
void attn_tc_kernel(const float* __restrict__ kqv, float* __restrict__ y) {
    extern __shared__ uint32_t smem[];
    uint32_t* sQ = smem;                    // also reused as sP
    uint32_t* sK = smem + 64 * QP_ST;
    uint32_t* sV = sK + 64 * KV_ST;

    const int qb  = blockIdx.x;
    const int h   = blockIdx.y;
    const int b   = blockIdx.z;
    const int tid = threadIdx.x;
    const int w   = tid >> 5;
    const int lane = tid & 31;
    const int g   = lane >> 2;
    const int q   = lane & 3;
    const int q0  = qb * 64;
    const int mrow = 16 * w;
    const float scale = 0.125f;  // 1/sqrt(64)

    // token stride in kqv = NH*3*HD = 3072; head base = h*192
    const size_t tokStride = (size_t)NH * 3 * HD;
    const size_t headOff   = (size_t)h * 3 * HD;

    // ---- load Q tile into sQ [qrow][hd], tf32 ----
    for (int idx = tid; idx < 64 * 16; idx += 128) {
        const int row = idx >> 4;
        const int c4  = (idx & 15) << 2;
        float4 v = *reinterpret_cast<const float4*>(
            &kqv[((size_t)(b * TT + q0 + row)) * tokStride + headOff + HD + c4]);
        uint32_t* dst = &sQ[row * QP_ST + c4];
        dst[0] = f2tf32(v.x); dst[1] = f2tf32(v.y);
        dst[2] = f2tf32(v.z); dst[3] = f2tf32(v.w);
    }
    __syncthreads();

    // ---- hoist Q fragments to registers (8 k-steps x 4 regs) ----
    uint32_t qf[8][4];
    #pragma unroll
    for (int ks = 0; ks < 8; ks++) {
        qf[ks][0] = sQ[(mrow + g) * QP_ST + ks * 8 + q];
        qf[ks][1] = sQ[(mrow + g + 8) * QP_ST + ks * 8 + q];
        qf[ks][2] = sQ[(mrow + g) * QP_ST + ks * 8 + q + 4];
        qf[ks][3] = sQ[(mrow + g + 8) * QP_ST + ks * 8 + q + 4];
    }

    float oacc[8][4];
    #pragma unroll
    for (int ni = 0; ni < 8; ni++)
        #pragma unroll
        for (int r = 0; r < 4; r++) oacc[ni][r] = 0.0f;
    float m_0 = -1e30f, m_1 = -1e30f, l_0 = 0.0f, l_1 = 0.0f;

    const int qrow0 = q0 + mrow + g;
    const int qrow1 = qrow0 + 8;

    for (int kb = 0; kb <= qb; kb++) {
        const int k0 = kb * 64;
        // ---- load K (transposed [hd][key]) and V ([key][hd]) ----
        for (int idx = tid; idx < 64 * 16; idx += 128) {
            // V: coalesced row-major
            const int vrow = idx >> 4;
            const int vc4  = (idx & 15) << 2;
            float4 vv = *reinterpret_cast<const float4*>(
                &kqv[((size_t)(b * TT + k0 + vrow)) * tokStride + headOff + 2 * HD + vc4]);
            uint32_t* vd = &sV[vrow * KV_ST + vc4];
            vd[0] = f2tf32(vv.x); vd[1] = f2tf32(vv.y);
            vd[2] = f2tf32(vv.z); vd[3] = f2tf32(vv.w);
            // K: row varies fastest (gather), conflict-free transpose STS
            const int krow = idx & 63;
            const int kc4  = (idx >> 6) << 2;
            float4 kv = *reinterpret_cast<const float4*>(
                &kqv[((size_t)(b * TT + k0 + krow)) * tokStride + headOff + kc4]);
            sK[(kc4 + 0) * KV_ST + krow] = f2tf32(kv.x);
            sK[(kc4 + 1) * KV_ST + krow] = f2tf32(kv.y);
            sK[(kc4 + 2) * KV_ST + krow] = f2tf32(kv.z);
            sK[(kc4 + 3) * KV_ST + krow] = f2tf32(kv.w);
        }
        __syncthreads();

        // ---- S = Q K^T ----
        float sa[8][4];
        #pragma unroll
        for (int ni = 0; ni < 8; ni++)
            #pragma unroll
            for (int r = 0; r < 4; r++) sa[ni][r] = 0.0f;

        #pragma unroll
        for (int ks = 0; ks < 8; ks++) {
            #pragma unroll
            for (int ni = 0; ni < 8; ni++) {
                uint32_t b0 = sK[(ks * 8 + q) * KV_ST + ni * 8 + g];
                uint32_t b1 = sK[(ks * 8 + q + 4) * KV_ST + ni * 8 + g];
                mma_tf32(sa[ni], qf[ks], b0, b1);
            }
        }

        // ---- scale + causal mask ----
        const bool diag = (kb == qb);
        #pragma unroll
        for (int ni = 0; ni < 8; ni++) {
            const int key = k0 + ni * 8 + 2 * q;
            sa[ni][0] = (diag && key     > qrow0) ? -1e30f : sa[ni][0] * scale;
            sa[ni][1] = (diag && key + 1 > qrow0) ? -1e30f : sa[ni][1] * scale;
            sa[ni][2] = (diag && key     > qrow1) ? -1e30f : sa[ni][2] * scale;
            sa[ni][3] = (diag && key + 1 > qrow1) ? -1e30f : sa[ni][3] * scale;
        }

        // ---- online softmax (rows g and g+8; quad = 4 lanes share a row) ----
        float mx0 = -1e30f, mx1 = -1e30f;
        #pragma unroll
        for (int ni = 0; ni < 8; ni++) {
            mx0 = fmaxf(mx0, fmaxf(sa[ni][0], sa[ni][1]));
            mx1 = fmaxf(mx1, fmaxf(sa[ni][2], sa[ni][3]));
        }
        mx0 = fmaxf(mx0, __shfl_xor_sync(0xffffffffu, mx0, 1));
        mx0 = fmaxf(mx0, __shfl_xor_sync(0xffffffffu, mx0, 2));
        mx1 = fmaxf(mx1, __shfl_xor_sync(0xffffffffu, mx1, 1));
        mx1 = fmaxf(mx1, __shfl_xor_sync(0xffffffffu, mx1, 2));
        const float mn0 = fmaxf(m_0, mx0);
        const float mn1 = fmaxf(m_1, mx1);
        const float al0 = __expf(m_0 - mn0);
        const float al1 = __expf(m_1 - mn1);
        float rs0 = 0.0f, rs1 = 0.0f;
        #pragma unroll
        for (int ni = 0; ni < 8; ni++) {
            sa[ni][0] = __expf(sa[ni][0] - mn0);
            sa[ni][1] = __expf(sa[ni][1] - mn0);
            sa[ni][2] = __expf(sa[ni][2] - mn1);
            sa[ni][3] = __expf(sa[ni][3] - mn1);
            rs0 += sa[ni][0] + sa[ni][1];
            rs1 += sa[ni][2] + sa[ni][3];
        }
        rs0 += __shfl_xor_sync(0xffffffffu, rs0, 1);
        rs0 += __shfl_xor_sync(0xffffffffu, rs0, 2);
        rs1 += __shfl_xor_sync(0xffffffffu, rs1, 1);
        rs1 += __shfl_xor_sync(0xffffffffu, rs1, 2);
        l_0 = l_0 * al0 + rs0;
        l_1 = l_1 * al1 + rs1;
        m_0 = mn0; m_1 = mn1;
        #pragma unroll
        for (int ni = 0; ni < 8; ni++) {
            oacc[ni][0] *= al0; oacc[ni][1] *= al0;
            oacc[ni][2] *= al1; oacc[ni][3] *= al1;
        }

        // ---- write P (tf32) into sP (= sQ region), warp-private rows ----
        uint32_t* sP = sQ;
        #pragma unroll
        for (int ni = 0; ni < 8; ni++) {
            const int c = ni * 8 + 2 * q;
            sP[(mrow + g) * QP_ST + c]     = f2tf32(sa[ni][0]);
            sP[(mrow + g) * QP_ST + c + 1] = f2tf32(sa[ni][1]);
            sP[(mrow + g + 8) * QP_ST + c]     = f2tf32(sa[ni][2]);
            sP[(mrow + g + 8) * QP_ST + c + 1] = f2tf32(sa[ni][3]);
        }
        __syncwarp();

        // ---- O += P @ V ----
        #pragma unroll
        for (int ks = 0; ks < 8; ks++) {
            uint32_t pa[4];
            pa[0] = sP[(mrow + g) * QP_ST + ks * 8 + q];
            pa[1] = sP[(mrow + g + 8) * QP_ST + ks * 8 + q];
            pa[2] = sP[(mrow + g) * QP_ST + ks * 8 + q + 4];
            pa[3] = sP[(mrow + g + 8) * QP_ST + ks * 8 + q + 4];
            #pragma unroll
            for (int ni = 0; ni < 8; ni++) {
                uint32_t b0 = sV[(ks * 8 + q) * KV_ST + ni * 8 + g];
                uint32_t b1 = sV[(ks * 8 + q + 4) * KV_ST + ni * 8 + g];
                mma_tf32(oacc[ni], pa, b0, b1);
            }
        }
        __syncthreads();  // protect sK/sV reuse next iteration
    }

    // ---- normalize + write y[b, t, h*64 + col] ----
    const float il0 = 1.0f / l_0;
    const float il1 = 1.0f / l_1;
    const int t0 = q0 + mrow + g;
    const int t1 = t0 + 8;
    #pragma unroll
    for (int ni = 0; ni < 8; ni++) {
        const int col = h * HD + ni * 8 + 2 * q;
        float2 v0 = make_float2(oacc[ni][0] * il0, oacc[ni][1] * il0);
        float2 v1 = make_float2(oacc[ni][2] * il1, oacc[ni][3] * il1);
        *reinterpret_cast<float2*>(&y[(size_t)(b * TT + t0) * CC + col]) = v0;
        *reinterpret_cast<float2*>(&y[(size_t)(b * TT + t1) * CC + col]) = v1;
    }
}

// ---------------------------------------------------------------------------
extern "C" void kernel_launch(void* const* d_in, const int* in_sizes, int n_in,
                              void* d_out, int out_size) {
    (void)in_sizes; (void)n_in; (void)out_size;
    const float* x      = (const float*)d_in[0];
    const float* W_kqv  = (const float*)d_in[1];
    const float* b_kqv  = (const float*)d_in[2];
    const float* W_proj = (const float*)d_in[3];
    const float* b_proj = (const float*)d_in[4];
    float* out = (float*)d_out;

    float* kqv = nullptr;
    float* y   = nullptr;
    cudaGetSymbolAddress((void**)&kqv, g_kqv);
    cudaGetSymbolAddress((void**)&y, g_y);

    cudaFuncSetAttribute(attn_tc_kernel, cudaFuncAttributeMaxDynamicSharedMemorySize,
                         ATT_SMEM_BYTES);

    // 1) kqv = x @ W_kqv^T + b_kqv   (M=4096, N=3072, K=1024)
    {
        dim3 grid(KQV3 / 128, BT / 128);
        gemm_tf32<<<grid, 256>>>(x, W_kqv, b_kqv, kqv, BT, KQV3, CC);
    }
    // 2) flash attention (tensor core) -> y
    {
        dim3 grid(TT / 64, NH, BB);
        attn_tc_kernel<<<grid, 128, ATT_SMEM_BYTES>>>(kqv, y);
    }
    // 3) out = y @ W_proj^T + b_proj (M=4096, N=1024, K=1024)
    {
        dim3 grid(CC / 128, BT / 128);
        gemm_tf32<<<grid, 256>>>(y, W_proj, b_proj, out, BT, CC, CC);
    }
}

// round 6
// speedup vs baseline: 3.9017x; 1.5986x over previous
#include <cuda_runtime.h>
#include <math.h>
#include <stdint.h>

// Problem constants
#define BB   2
#define TT   2048
#define CC   1024
#define NH   16
#define HD   64
#define BT   (BB * TT)        // 4096
#define KQV3 (3 * CC)         // 3072

// Scratch (allocation-free rule: __device__ globals)
__device__ float g_kqv[(size_t)BT * KQV3];  // (B,T,nh,3,hd) packed, fp32
__device__ float g_y[(size_t)BT * CC];      // attention output, fp32

// ---------------------------------------------------------------------------
// Helpers
// ---------------------------------------------------------------------------
__device__ __forceinline__ uint32_t f2tf32(float x) {
    uint32_t r;
    asm("cvt.rna.tf32.f32 %0, %1;" : "=r"(r) : "f"(x));
    return r;
}
__device__ __forceinline__ uint32_t s2tf32(uint32_t raw) {
    return f2tf32(__uint_as_float(raw));
}

__device__ __forceinline__ void mma_tf32(float* c, const uint32_t* a,
                                         uint32_t b0, uint32_t b1) {
    asm volatile(
        "mma.sync.aligned.m16n8k8.row.col.f32.tf32.tf32.f32 "
        "{%0,%1,%2,%3}, {%4,%5,%6,%7}, {%8,%9}, {%0,%1,%2,%3};\n"
        : "+f"(c[0]), "+f"(c[1]), "+f"(c[2]), "+f"(c[3])
        : "r"(a[0]), "r"(a[1]), "r"(a[2]), "r"(a[3]), "r"(b0), "r"(b1));
}

__device__ __forceinline__ void cpa16(uint32_t saddr, const void* gptr) {
    asm volatile("cp.async.cg.shared.global [%0], [%1], 16;" :: "r"(saddr), "l"(gptr));
}
__device__ __forceinline__ void cpcommit() {
    asm volatile("cp.async.commit_group;" ::: "memory");
}
template <int N>
__device__ __forceinline__ void cpwait() {
    asm volatile("cp.async.wait_group %0;" :: "n"(N) : "memory");
}

// ---------------------------------------------------------------------------
// tf32 tensor-core GEMM with 3-stage cp.async pipeline.
// C[m,n] = sum_k A[m,k]*W[n,k] + bias[n].  BM=BN=128, BK=16. 256 thr, 8 warps
// (2m x 4n), warp tile 64x32. smem raw fp32 [row][k] stride 20; tf32 cvt at
// fragment load ((20g+q) mod 32 all-distinct -> conflict-free).
// ---------------------------------------------------------------------------
#define GPAD     20
#define GTILEW   (128 * GPAD)          // 2560 words / tile
#define GSTAGEW  (2 * GTILEW)          // 5120 words / stage (A+W)
#define GSTAGES  3
#define GSMEM_BYTES (GSTAGES * GSTAGEW * 4)   // 61440

__global__ __launch_bounds__(256)
void gemm_tf32(const float* __restrict__ A, const float* __restrict__ W,
               const float* __restrict__ bias, float* __restrict__ Cmat,
               int M, int N, int K) {
    extern __shared__ uint32_t gsm[];

    const int tid  = threadIdx.x;
    const int lane = tid & 31;
    const int wid  = tid >> 5;
    const int g    = lane >> 2;
    const int q    = lane & 3;
    const int wm   = wid >> 2;
    const int wn   = wid & 3;

    const int m0 = blockIdx.y * 128;
    const int n0 = blockIdx.x * 128;
    const float* Abase = A + (size_t)m0 * K;
    const float* Wbase = W + (size_t)n0 * K;
    const int niter = K >> 4;

    // two 16B chunks per thread per tile: chunk c -> row c>>2, k4 (c&3)*4
    const int r0  = tid >> 2,          k40 = (tid & 3) << 2;
    const int r1  = (tid + 256) >> 2,  k41 = ((tid + 256) & 3) << 2;

    float acc[4][4][4];
    #pragma unroll
    for (int mi = 0; mi < 4; mi++)
        #pragma unroll
        for (int ni = 0; ni < 4; ni++)
            #pragma unroll
            for (int r = 0; r < 4; r++) acc[mi][ni][r] = 0.0f;

    // prologue: issue tiles 0,1
    #pragma unroll
    for (int p = 0; p < GSTAGES - 1; p++) {
        if (p < niter) {
            const int kb = p << 4;
            uint32_t sb = (uint32_t)__cvta_generic_to_shared(gsm + p * GSTAGEW);
            cpa16(sb + (r0 * GPAD + k40) * 4, Abase + (size_t)r0 * K + kb + k40);
            cpa16(sb + (r1 * GPAD + k41) * 4, Abase + (size_t)r1 * K + kb + k41);
            uint32_t wb = sb + GTILEW * 4;
            cpa16(wb + (r0 * GPAD + k40) * 4, Wbase + (size_t)r0 * K + kb + k40);
            cpa16(wb + (r1 * GPAD + k41) * 4, Wbase + (size_t)r1 * K + kb + k41);
        }
        cpcommit();
    }

    for (int i = 0; i < niter; i++) {
        // issue tile i+2
        if (i + 2 < niter) {
            const int ii = i + 2;
            const int kb = ii << 4;
            uint32_t sb = (uint32_t)__cvta_generic_to_shared(
                gsm + (ii % GSTAGES) * GSTAGEW);
            cpa16(sb + (r0 * GPAD + k40) * 4, Abase + (size_t)r0 * K + kb + k40);
            cpa16(sb + (r1 * GPAD + k41) * 4, Abase + (size_t)r1 * K + kb + k41);
            uint32_t wb = sb + GTILEW * 4;
            cpa16(wb + (r0 * GPAD + k40) * 4, Wbase + (size_t)r0 * K + kb + k40);
            cpa16(wb + (r1 * GPAD + k41) * 4, Wbase + (size_t)r1 * K + kb + k41);
        }
        cpcommit();
        cpwait<GSTAGES - 1>();   // tile i is (stages-1) commits old -> resident
        __syncthreads();

        const uint32_t* sa = gsm + (i % GSTAGES) * GSTAGEW;
        const uint32_t* sw = sa + GTILEW;

        #pragma unroll
        for (int ks = 0; ks < 16; ks += 8) {
            uint32_t af[4][4];
            uint32_t bf[4][2];
            #pragma unroll
            for (int mi = 0; mi < 4; mi++) {
                const int m = wm * 64 + mi * 16;
                af[mi][0] = s2tf32(sa[(m + g) * GPAD + ks + q]);
                af[mi][1] = s2tf32(sa[(m + g + 8) * GPAD + ks + q]);
                af[mi][2] = s2tf32(sa[(m + g) * GPAD + ks + q + 4]);
                af[mi][3] = s2tf32(sa[(m + g + 8) * GPAD + ks + q + 4]);
            }
            #pragma unroll
            for (int ni = 0; ni < 4; ni++) {
                const int n = wn * 32 + ni * 8;
                bf[ni][0] = s2tf32(sw[(n + g) * GPAD + ks + q]);
                bf[ni][1] = s2tf32(sw[(n + g) * GPAD + ks + q + 4]);
            }
            #pragma unroll
            for (int mi = 0; mi < 4; mi++)
                #pragma unroll
                for (int ni = 0; ni < 4; ni++)
                    mma_tf32(acc[mi][ni], af[mi], bf[ni][0], bf[ni][1]);
        }
        __syncthreads();  // all reads of stage i%3 done before it is rewritten
    }

    // epilogue: + bias, fp32 out
    #pragma unroll
    for (int mi = 0; mi < 4; mi++) {
        const int m = m0 + wm * 64 + mi * 16 + g;
        #pragma unroll
        for (int ni = 0; ni < 4; ni++) {
            const int n = n0 + wn * 32 + ni * 8 + 2 * q;
            const float b0 = __ldg(&bias[n]);
            const float b1 = __ldg(&bias[n + 1]);
            float2 v0 = make_float2(acc[mi][ni][0] + b0, acc[mi][ni][1] + b1);
            float2 v1 = make_float2(acc[mi][ni][2] + b0, acc[mi][ni][3] + b1);
            *reinterpret_cast<float2*>(&Cmat[(size_t)m * N + n]) = v0;
            *reinterpret_cast<float2*>(&Cmat[(size_t)(m + 8) * N + n]) = v1;
        }
    }
}

// ---------------------------------------------------------------------------
// Flash attention, tf32 mma, cp.async double-buffered K/V.
// Grid (T/64, NH, B), 128 threads (4 warps), warp owns 16 q-rows.
// sQ raw fp32 [row][hd] stride 68 (reused as tf32 sP);
// sK, sV raw fp32 [key][hd] stride 72, 2 stages.
// Fragment reads conflict-free: K (8g+q), V (8q+g) mod 32 all-distinct.
// ---------------------------------------------------------------------------
#define QP_ST 68
#define KV_ST 72
#define QW  (64 * QP_ST)       // 4352 words
#define KVW (64 * KV_ST)       // 4608 words
#define ASTW (2 * KVW)         // 9216 words per stage (K+V)
#define ATT_BYTES ((QW + 2 * ASTW) * 4)   // 91136

__global__ __launch_bounds__(128)
void attn_tc_kernel(const float* __restrict__ kqv, float* __restrict__ y) {
    extern __shared__ uint32_t smem[];
    uint32_t* sQ = smem;  // raw fp32 Q; later tf32 P

    const int qb  = blockIdx.x;
    const int h   = blockIdx.y;
    const int b   = blockIdx.z;
    const int tid = threadIdx.x;
    const int w   = tid >> 5;
    const int lane = tid & 31;
    const int g   = lane >> 2;
    const int q   = lane & 3;
    const int q0  = qb * 64;
    const int mrow = 16 * w;
    const float scale = 0.125f;

    const size_t tokStride = (size_t)NH * 3 * HD;   // 3072
    const size_t headOff   = (size_t)h * 3 * HD;    // h*192

    // issue K+V tile kb into stage kb&1 (16 cp.async per thread)
    auto issueKV = [&](int kb) {
        const int k0 = kb * 64;
        uint32_t base = (uint32_t)__cvta_generic_to_shared(
            smem + QW + (kb & 1) * ASTW);
        #pragma unroll
        for (int j = 0; j < 8; j++) {
            const int c   = tid + j * 128;
            const int row = c >> 4;
            const int c4  = (c & 15) << 2;
            const float* gk =
                &kqv[((size_t)(b * TT + k0 + row)) * tokStride + headOff + c4];
            cpa16(base + (row * KV_ST + c4) * 4, gk);               // K (sel 0)
            cpa16(base + (KVW + row * KV_ST + c4) * 4, gk + 2 * HD); // V (sel 2)
        }
    };

    issueKV(0);
    cpcommit();

    // load Q tile raw fp32
    for (int idx = tid; idx < 64 * 16; idx += 128) {
        const int row = idx >> 4;
        const int c4  = (idx & 15) << 2;
        float4 v = *reinterpret_cast<const float4*>(
            &kqv[((size_t)(b * TT + q0 + row)) * tokStride + headOff + HD + c4]);
        uint32_t* dst = &sQ[row * QP_ST + c4];
        dst[0] = __float_as_uint(v.x); dst[1] = __float_as_uint(v.y);
        dst[2] = __float_as_uint(v.z); dst[3] = __float_as_uint(v.w);
    }
    __syncthreads();

    // hoist Q fragments (tf32)
    uint32_t qf[8][4];
    #pragma unroll
    for (int ks = 0; ks < 8; ks++) {
        qf[ks][0] = s2tf32(sQ[(mrow + g) * QP_ST + ks * 8 + q]);
        qf[ks][1] = s2tf32(sQ[(mrow + g + 8) * QP_ST + ks * 8 + q]);
        qf[ks][2] = s2tf32(sQ[(mrow + g) * QP_ST + ks * 8 + q + 4]);
        qf[ks][3] = s2tf32(sQ[(mrow + g + 8) * QP_ST + ks * 8 + q + 4]);
    }

    float oacc[8][4];
    #pragma unroll
    for (int ni = 0; ni < 8; ni++)
        #pragma unroll
        for (int r = 0; r < 4; r++) oacc[ni][r] = 0.0f;
    float m_0 = -1e30f, m_1 = -1e30f, l_0 = 0.0f, l_1 = 0.0f;

    const int qrow0 = q0 + mrow + g;
    const int qrow1 = qrow0 + 8;

    for (int kb = 0; kb <= qb; kb++) {
        const int k0 = kb * 64;
        if (kb + 1 <= qb) issueKV(kb + 1);
        cpcommit();
        cpwait<1>();      // tile kb is 2nd-newest commit -> resident
        __syncthreads();

        const uint32_t* sK = smem + QW + (kb & 1) * ASTW;
        const uint32_t* sV = sK + KVW;

        // ---- S = Q K^T ----
        float sa[8][4];
        #pragma unroll
        for (int ni = 0; ni < 8; ni++)
            #pragma unroll
            for (int r = 0; r < 4; r++) sa[ni][r] = 0.0f;

        #pragma unroll
        for (int ks = 0; ks < 8; ks++) {
            #pragma unroll
            for (int ni = 0; ni < 8; ni++) {
                uint32_t b0 = s2tf32(sK[(ni * 8 + g) * KV_ST + ks * 8 + q]);
                uint32_t b1 = s2tf32(sK[(ni * 8 + g) * KV_ST + ks * 8 + q + 4]);
                mma_tf32(sa[ni], qf[ks], b0, b1);
            }
        }

        // ---- scale + causal mask ----
        const bool diag = (kb == qb);
        #pragma unroll
        for (int ni = 0; ni < 8; ni++) {
            const int key = k0 + ni * 8 + 2 * q;
            sa[ni][0] = (diag && key     > qrow0) ? -1e30f : sa[ni][0] * scale;
            sa[ni][1] = (diag && key + 1 > qrow0) ? -1e30f : sa[ni][1] * scale;
            sa[ni][2] = (diag && key     > qrow1) ? -1e30f : sa[ni][2] * scale;
            sa[ni][3] = (diag && key + 1 > qrow1) ? -1e30f : sa[ni][3] * scale;
        }

        // ---- online softmax (rows g, g+8; 4-lane quad shares a row) ----
        float mx0 = -1e30f, mx1 = -1e30f;
        #pragma unroll
        for (int ni = 0; ni < 8; ni++) {
            mx0 = fmaxf(mx0, fmaxf(sa[ni][0], sa[ni][1]));
            mx1 = fmaxf(mx1, fmaxf(sa[ni][2], sa[ni][3]));
        }
        mx0 = fmaxf(mx0, __shfl_xor_sync(0xffffffffu, mx0, 1));
        mx0 = fmaxf(mx0, __shfl_xor_sync(0xffffffffu, mx0, 2));
        mx1 = fmaxf(mx1, __shfl_xor_sync(0xffffffffu, mx1, 1));
        mx1 = fmaxf(mx1, __shfl_xor_sync(0xffffffffu, mx1, 2));
        const float mn0 = fmaxf(m_0, mx0);
        const float mn1 = fmaxf(m_1, mx1);
        const float al0 = __expf(m_0 - mn0);
        const float al1 = __expf(m_1 - mn1);
        float rs0 = 0.0f, rs1 = 0.0f;
        #pragma unroll
        for (int ni = 0; ni < 8; ni++) {
            sa[ni][0] = __expf(sa[ni][0] - mn0);
            sa[ni][1] = __expf(sa[ni][1] - mn0);
            sa[ni][2] = __expf(sa[ni][2] - mn1);
            sa[ni][3] = __expf(sa[ni][3] - mn1);
            rs0 += sa[ni][0] + sa[ni][1];
            rs1 += sa[ni][2] + sa[ni][3];
        }
        rs0 += __shfl_xor_sync(0xffffffffu, rs0, 1);
        rs0 += __shfl_xor_sync(0xffffffffu, rs0, 2);
        rs1 += __shfl_xor_sync(0xffffffffu, rs1, 1);
        rs1 += __shfl_xor_sync(0xffffffffu, rs1, 2);
        l_0 = l_0 * al0 + rs0;
        l_1 = l_1 * al1 + rs1;
        m_0 = mn0; m_1 = mn1;
        #pragma unroll
        for (int ni = 0; ni < 8; ni++) {
            oacc[ni][0] *= al0; oacc[ni][1] *= al0;
            oacc[ni][2] *= al1; oacc[ni][3] *= al1;
        }

        // ---- write P (tf32) into sP (= sQ), warp-private rows ----
        uint32_t* sP = sQ;
        #pragma unroll
        for (int ni = 0; ni < 8; ni++) {
            const int c = ni * 8 + 2 * q;
            sP[(mrow + g) * QP_ST + c]         = f2tf32(sa[ni][0]);
            sP[(mrow + g) * QP_ST + c + 1]     = f2tf32(sa[ni][1]);
            sP[(mrow + g + 8) * QP_ST + c]     = f2tf32(sa[ni][2]);
            sP[(mrow + g + 8) * QP_ST + c + 1] = f2tf32(sa[ni][3]);
        }
        __syncwarp();

        // ---- O += P @ V ----
        #pragma unroll
        for (int ks = 0; ks < 8; ks++) {
            uint32_t pa[4];
            pa[0] = sP[(mrow + g) * QP_ST + ks * 8 + q];
            pa[1] = sP[(mrow + g + 8) * QP_ST + ks * 8 + q];
            pa[2] = sP[(mrow + g) * QP_ST + ks * 8 + q + 4];
            pa[3] = sP[(mrow + g + 8) * QP_ST + ks * 8 + q + 4];
            #pragma unroll
            for (int ni = 0; ni < 8; ni++) {
                uint32_t b0 = s2tf32(sV[(ks * 8 + q) * KV_ST + ni * 8 + g]);
                uint32_t b1 = s2tf32(sV[(ks * 8 + q + 4) * KV_ST + ni * 8 + g]);
                mma_tf32(oacc[ni], pa, b0, b1);
            }
        }
        __syncthreads();  // stage kb&1 fully read before rewrite at kb+2
    }

    // ---- normalize + write y[b, t, h*64 + col] ----
    const float il0 = 1.0f / l_0;
    const float il1 = 1.0f / l_1;
    const int t0 = q0 + mrow + g;
    const int t1 = t0 + 8;
    #pragma unroll
    for (int ni = 0; ni < 8; ni++) {
        const int col = h * HD + ni * 8 + 2 * q;
        float2 v0 = make_float2(oacc[ni][0] * il0, oacc[ni][1] * il0);
        float2 v1 = make_float2(oacc[ni][2] * il1, oacc[ni][3] * il1);
        *reinterpret_cast<float2*>(&y[(size_t)(b * TT + t0) * CC + col]) = v0;
        *reinterpret_cast<float2*>(&y[(size_t)(b * TT + t1) * CC + col]) = v1;
    }
}

// ---------------------------------------------------------------------------
extern "C" void kernel_launch(void* const* d_in, const int* in_sizes, int n_in,
                              void* d_out, int out_size) {
    (void)in_sizes; (void)n_in; (void)out_size;
    const float* x      = (const float*)d_in[0];
    const float* W_kqv  = (const float*)d_in[1];
    const float* b_kqv  = (const float*)d_in[2];
    const float* W_proj = (const float*)d_in[3];
    const float* b_proj = (const float*)d_in[4];
    float* out = (float*)d_out;

    float* kqv = nullptr;
    float* y   = nullptr;
    cudaGetSymbolAddress((void**)&kqv, g_kqv);
    cudaGetSymbolAddress((void**)&y, g_y);

    cudaFuncSetAttribute(gemm_tf32, cudaFuncAttributeMaxDynamicSharedMemorySize,
                         GSMEM_BYTES);
    cudaFuncSetAttribute(attn_tc_kernel, cudaFuncAttributeMaxDynamicSharedMemorySize,
                         ATT_BYTES);

    // 1) kqv = x @ W_kqv^T + b_kqv   (M=4096, N=3072, K=1024)
    {
        dim3 grid(KQV3 / 128, BT / 128);
        gemm_tf32<<<grid, 256, GSMEM_BYTES>>>(x, W_kqv, b_kqv, kqv, BT, KQV3, CC);
    }
    // 2) flash attention (tensor core) -> y
    {
        dim3 grid(TT / 64, NH, BB);
        attn_tc_kernel<<<grid, 128, ATT_BYTES>>>(kqv, y);
    }
    // 3) out = y @ W_proj^T + b_proj (M=4096, N=1024, K=1024)
    {
        dim3 grid(CC / 128, BT / 128);
        gemm_tf32<<<grid, 256, GSMEM_BYTES>>>(y, W_proj, b_proj, out, BT, CC, CC);
    }
}